// round 10
// baseline (speedup 1.0000x reference)
#include <cuda_runtime.h>
#include <math.h>

// ChamferLoss: bs=4, npts=4096, dim=3. Fully fused: each dist^2 computed once.
// x in REGISTERS (each lane owns 16 x -> col-mins in regs, no shfl/atomics);
// y broadcast from smem (pre-duplicated packed pairs). Row-min: one 5-shfl bfly
// per (y, warp). dist^2 = ||x||^2 + ||y||^2 - 2 x.y via packed f32x2, chain seeded
// with add2(H, ysq) so value is complete for both row and col mins.
// Grid: 32 y-blocks x 4 batches = 128 blocks (one wave). Per-batch finishers via
// self-resetting counters (deterministic, graph-replayable).

#define NPTS 4096
#define BS   4
#define TPB  256
#define NWARP 8
#define YB   128                 // y rows per block
#define NYB  (NPTS / YB)         // 32 y-blocks per batch
#define XPW  512                 // x per warp (8 warps cover all 4096)
#define SLOTS 8                  // packed x-pairs per lane (16 x per lane)

__device__ float g_colpart[BS * NYB * NPTS];   // [b][yb][x]
__device__ float g_rowsum[BS * NYB];
__device__ float g_bsum[BS];
__device__ unsigned int g_bc[BS];              // zero-init, self-resetting
__device__ unsigned int g_fc;                  // zero-init, self-resetting

typedef unsigned long long ull;

__device__ __forceinline__ ull pack2(float a, float b) {
    ull v;
    asm("mov.b64 %0, {%1, %2};" : "=l"(v) : "r"(__float_as_uint(a)), "r"(__float_as_uint(b)));
    return v;
}
__device__ __forceinline__ void unpack2(ull v, float& a, float& b) {
    unsigned lo, hi;
    asm("mov.b64 {%0, %1}, %2;" : "=r"(lo), "=r"(hi) : "l"(v));
    a = __uint_as_float(lo); b = __uint_as_float(hi);
}
__device__ __forceinline__ ull fma2(ull a, ull b, ull c) {
    ull d;
    asm("fma.rn.f32x2 %0, %1, %2, %3;" : "=l"(d) : "l"(a), "l"(b), "l"(c));
    return d;
}
__device__ __forceinline__ ull add2(ull a, ull b) {
    ull d;
    asm("add.rn.f32x2 %0, %1, %2;" : "=l"(d) : "l"(a), "l"(b));
    return d;
}

__global__ __launch_bounds__(TPB, 1) void chamfer_fused(
    const float* __restrict__ x, const float* __restrict__ y, float* __restrict__ out)
{
    __shared__ __align__(16) float sy[YB * 8];       // per y: {yx,yx,yy,yy,yz,yz,ysq,ysq}
    __shared__ __align__(16) float srow[YB * NWARP]; // [y][warp]
    __shared__ float red[NWARP];
    __shared__ int   s_last;

    const int tid  = threadIdx.x;
    const int lane = tid & 31;
    const int w    = tid >> 5;
    const int yb   = blockIdx.x;          // 0..NYB-1
    const int b    = blockIdx.y;          // 0..BS-1

    // Stage y-tile, components duplicated into packed-pair layout.
    for (int i = tid; i < YB; i += TPB) {
        const float* yp = y + ((size_t)b * NPTS + (size_t)yb * YB + i) * 3;
        float a = yp[0], c = yp[1], d = yp[2];
        float qs = fmaf(a, a, fmaf(c, c, d * d));
        float* o = sy + i * 8;
        o[0] = a; o[1] = a; o[2] = c; o[3] = c;
        o[4] = d; o[5] = d; o[6] = qs; o[7] = qs;
    }

    // Each lane loads its 16 x-points into packed registers.
    ull Xp[SLOTS], Yq[SLOTS], Zp[SLOTS], Hp[SLOTS];
    {
        const float* xb = x + ((size_t)b * NPTS + (size_t)w * XPW) * 3;
        #pragma unroll
        for (int j = 0; j < SLOTS; ++j) {
            int i0 = (2 * j) * 32 + lane;
            int i1 = i0 + 32;
            float x0 = xb[3 * i0 + 0], y0 = xb[3 * i0 + 1], z0 = xb[3 * i0 + 2];
            float x1 = xb[3 * i1 + 0], y1 = xb[3 * i1 + 1], z1 = xb[3 * i1 + 2];
            Xp[j] = pack2(-2.0f * x0, -2.0f * x1);
            Yq[j] = pack2(-2.0f * y0, -2.0f * y1);
            Zp[j] = pack2(-2.0f * z0, -2.0f * z1);
            Hp[j] = pack2(fmaf(x0, x0, fmaf(y0, y0, z0 * z0)),
                          fmaf(x1, x1, fmaf(y1, y1, z1 * z1)));
        }
    }

    float colacc[2 * SLOTS];
    #pragma unroll
    for (int k = 0; k < 2 * SLOTS; ++k) colacc[k] = 3.402823466e+38f;

    __syncthreads();

    unsigned sya = (unsigned)__cvta_generic_to_shared(sy);

    #pragma unroll 2
    for (int yy = 0; yy < YB; ++yy, sya += 32) {
        ull Ya, Yb_, Yc, Ys;
        asm("ld.shared.v2.u64 {%0,%1}, [%2];"    : "=l"(Ya), "=l"(Yb_) : "r"(sya));
        asm("ld.shared.v2.u64 {%0,%1}, [%2+16];" : "=l"(Yc), "=l"(Ys)  : "r"(sya));

        float rm[SLOTS];
        #pragma unroll
        for (int j = 0; j < SLOTS; ++j) {
            ull t = add2(Hp[j], Ys);
            t = fma2(Xp[j], Ya, t);
            t = fma2(Yq[j], Yb_, t);
            t = fma2(Zp[j], Yc, t);
            float a, bv;
            unpack2(t, a, bv);
            colacc[2 * j]     = fminf(colacc[2 * j], a);
            colacc[2 * j + 1] = fminf(colacc[2 * j + 1], bv);
            rm[j] = fminf(a, bv);
        }
        float r0 = fminf(fminf(rm[0], rm[1]), fminf(rm[2], rm[3]));
        float r1 = fminf(fminf(rm[4], rm[5]), fminf(rm[6], rm[7]));
        float rc = fminf(r0, r1);
        #pragma unroll
        for (int off = 16; off; off >>= 1)
            rc = fminf(rc, __shfl_xor_sync(0xFFFFFFFFu, rc, off));
        if (lane == 0) srow[yy * NWARP + w] = rc;
    }

    __syncthreads();

    // Row combine (min over 8 warps) + per-block row sum of sqrt.
    float rsum = 0.0f;
    if (tid < YB) {
        const float4* p = (const float4*)&srow[tid * NWARP];
        float4 A = p[0], B = p[1];
        float m = fminf(fminf(fminf(A.x, A.y), fminf(A.z, A.w)),
                        fminf(fminf(B.x, B.y), fminf(B.z, B.w)));
        rsum = sqrtf(1e-6f + m);
    }
    #pragma unroll
    for (int off = 16; off; off >>= 1)
        rsum += __shfl_down_sync(0xFFFFFFFFu, rsum, off);
    if (lane == 0) red[w] = rsum;
    __syncthreads();
    if (tid == 0) {
        float t = 0.0f;
        #pragma unroll
        for (int i = 0; i < NWARP; ++i) t += red[i];
        g_rowsum[b * NYB + yb] = t;
    }

    // Col partials -> global (coalesced: lanes write consecutive x).
    {
        float* cp = &g_colpart[((size_t)b * NYB + yb) * NPTS + (size_t)w * XPW];
        #pragma unroll
        for (int kk = 0; kk < 2 * SLOTS; ++kk)
            cp[kk * 32 + lane] = colacc[kk];
    }

    // ---- Per-batch finisher (last of the 32 y-blocks). ----
    __threadfence();
    if (tid == 0)
        s_last = (atomicAdd(&g_bc[b], 1u) == NYB - 1) ? 1 : 0;
    __syncthreads();

    if (s_last) {
        if (tid == 0) g_bc[b] = 0;        // self-reset for graph replay
        float acc = 0.0f;
        for (int xi = tid; xi < NPTS; xi += TPB) {   // 16 x's per thread
            float m = 3.402823466e+38f;
            #pragma unroll 8
            for (int u = 0; u < NYB; ++u)
                m = fminf(m, __ldcg(&g_colpart[((size_t)b * NYB + u) * NPTS + xi]));
            acc += sqrtf(1e-6f + m);
        }
        if (tid < NYB) acc += __ldcg(&g_rowsum[b * NYB + tid]);

        #pragma unroll
        for (int off = 16; off; off >>= 1)
            acc += __shfl_down_sync(0xFFFFFFFFu, acc, off);
        if (lane == 0) red[w] = acc;
        __syncthreads();
        if (tid == 0) {
            float t = 0.0f;
            #pragma unroll
            for (int i = 0; i < NWARP; ++i) t += red[i];
            g_bsum[b] = t;
            __threadfence();
            if (atomicAdd(&g_fc, 1u) == BS - 1) {
                volatile float* gs = g_bsum;
                float tot = gs[0] + gs[1] + gs[2] + gs[3];
                out[0] = tot * (1.0f / 16384.0f);   // (S1 + S2) / (BS * NPTS)
                g_fc = 0;                            // self-reset
            }
        }
    }
}

extern "C" void kernel_launch(void* const* d_in, const int* in_sizes, int n_in,
                              void* d_out, int out_size)
{
    const float* x = (const float*)d_in[0];
    const float* y = (const float*)d_in[1];
    float* out = (float*)d_out;

    chamfer_fused<<<dim3(NYB, BS), TPB>>>(x, y, out);
}

// round 11
// speedup vs baseline: 1.8597x; 1.8597x over previous
#include <cuda_runtime.h>
#include <math.h>

// ChamferLoss: bs=4, npts=4096, dim=3.
// dist^2(q,r) = ||q||^2 + (||r||^2 - 2 q.r); minimize squared dist, sqrt once.
// R6 structure (Q=4 queries/thread, RS=4 ref splits, 128 blocks x 256 = one wave)
// + explicit register double-buffering: next ref group's 4 LDS.128 issue before
// the current group's FMA block, hiding the 29-cyc LDS latency.
// Distributed epilogue via self-resetting counters (deterministic, replayable).

#define NPTS 4096
#define BS   4
#define TPB  256
#define Q    4                       // queries per thread
#define RS   4                       // reference splits
#define RPB  (NPTS / RS)             // 1024 refs per block
#define QPB  (TPB * Q)               // 1024 queries per block
#define NQT  (NPTS / QPB)            // 4 query tiles
#define NGRP (NQT * BS * 2)          // 32 query-tile groups
#define NBLK (NGRP * RS)             // 128 blocks == one balanced wave
#define NGROUPS (RPB / 4)            // 256 ref groups per block

__device__ float g_pmin[2 * BS * NPTS * RS];   // [dir][b][q][rs]
__device__ float g_gsum[NGRP];
__device__ unsigned int g_gc[NGRP];            // zero-init, self-resetting
__device__ unsigned int g_fc;                  // zero-init, self-resetting

typedef unsigned long long ull;

__device__ __forceinline__ ull bcast2(float f) {
    ull v;
    asm("mov.b64 %0, {%1, %1};" : "=l"(v) : "r"(__float_as_uint(f)));
    return v;
}
__device__ __forceinline__ void unpack2(ull v, float& a, float& b) {
    unsigned lo, hi;
    asm("mov.b64 {%0, %1}, %2;" : "=r"(lo), "=r"(hi) : "l"(v));
    a = __uint_as_float(lo); b = __uint_as_float(hi);
}

struct Grp { ull X01, X23, Y01, Y23, Z01, Z23, H01, H23; };

__device__ __forceinline__ void load_grp(Grp& g, unsigned sa) {
    asm("ld.shared.v2.u64 {%0,%1}, [%2];"    : "=l"(g.X01), "=l"(g.X23) : "r"(sa));
    asm("ld.shared.v2.u64 {%0,%1}, [%2+16];" : "=l"(g.Y01), "=l"(g.Y23) : "r"(sa));
    asm("ld.shared.v2.u64 {%0,%1}, [%2+32];" : "=l"(g.Z01), "=l"(g.Z23) : "r"(sa));
    asm("ld.shared.v2.u64 {%0,%1}, [%2+48];" : "=l"(g.H01), "=l"(g.H23) : "r"(sa));
}

__global__ __launch_bounds__(TPB, 1) void chamfer_main(
    const float* __restrict__ x, const float* __restrict__ y, float* __restrict__ out)
{
    __shared__ float s[RPB * 4 + 16];     // 16 KB + 64B pad group (prefetch overrun)
    __shared__ float red[8];
    __shared__ int   s_last;

    const int tid = threadIdx.x;
    const int qt  = blockIdx.x;           // 0..NQT-1
    const int b   = blockIdx.y;           // 0..BS-1
    const int z   = blockIdx.z;           // 0..2*RS-1
    const int dir = z >> 2;               // z / RS
    const int rs  = z & 3;                // z % RS

    const float* __restrict__ q  = dir ? y : x;
    const float* __restrict__ r  = dir ? x : y;
    const float* __restrict__ rb = r + ((size_t)b * NPTS + (size_t)rs * RPB) * 3;

    // Stage this block's reference slice: -2r (SoA groups of 4) and ||r||^2.
    #pragma unroll 4
    for (int i = tid; i < RPB; i += TPB) {
        float rx = rb[3 * i + 0];
        float ry = rb[3 * i + 1];
        float rz = rb[3 * i + 2];
        float* base = s + ((i >> 2) << 4) + (i & 3);
        base[0]  = -2.0f * rx;
        base[4]  = -2.0f * ry;
        base[8]  = -2.0f * rz;
        base[12] = fmaf(rx, rx, fmaf(ry, ry, rz * rz));
    }
    if (tid < 16) s[RPB * 4 + tid] = 0.0f;   // pad group (values unused)

    // Q=4 query points per thread (coalesced loads within each k).
    const int qbase = qt * QPB + tid;
    ull bx[Q], by[Q], bz[Q];
    float qsq[Q];
    #pragma unroll
    for (int k = 0; k < Q; ++k) {
        const float* qp = q + ((size_t)b * NPTS + (qbase + k * TPB)) * 3;
        float qx = qp[0], qy = qp[1], qz = qp[2];
        qsq[k] = fmaf(qx, qx, fmaf(qy, qy, qz * qz));
        bx[k] = bcast2(qx); by[k] = bcast2(qy); bz[k] = bcast2(qz);
    }

    __syncthreads();

    unsigned sa = (unsigned)__cvta_generic_to_shared(s);
    float mac[Q][4];
    #pragma unroll
    for (int k = 0; k < Q; ++k) {
        mac[k][0] = 3.402823466e+38f; mac[k][1] = 3.402823466e+38f;
        mac[k][2] = 3.402823466e+38f; mac[k][3] = 3.402823466e+38f;
    }

    Grp A, B;
    load_grp(A, sa);                       // preload group 0

    #define COMPUTE(G)                                                              \
        _Pragma("unroll")                                                           \
        for (int k = 0; k < Q; ++k) {                                               \
            ull t0, t1;                                                             \
            asm("fma.rn.f32x2 %0, %1, %2, %3;" : "=l"(t0)                           \
                : "l"(bz[k]), "l"((G).Z01), "l"((G).H01));                          \
            asm("fma.rn.f32x2 %0, %1, %2, %0;" : "+l"(t0)                           \
                : "l"(by[k]), "l"((G).Y01));                                        \
            asm("fma.rn.f32x2 %0, %1, %2, %0;" : "+l"(t0)                           \
                : "l"(bx[k]), "l"((G).X01));                                        \
            asm("fma.rn.f32x2 %0, %1, %2, %3;" : "=l"(t1)                           \
                : "l"(bz[k]), "l"((G).Z23), "l"((G).H23));                          \
            asm("fma.rn.f32x2 %0, %1, %2, %0;" : "+l"(t1)                           \
                : "l"(by[k]), "l"((G).Y23));                                        \
            asm("fma.rn.f32x2 %0, %1, %2, %0;" : "+l"(t1)                           \
                : "l"(bx[k]), "l"((G).X23));                                        \
            float a0, a1, a2, a3;                                                   \
            unpack2(t0, a0, a1);                                                    \
            unpack2(t1, a2, a3);                                                    \
            mac[k][0] = fminf(mac[k][0], a0);                                       \
            mac[k][1] = fminf(mac[k][1], a1);                                       \
            mac[k][2] = fminf(mac[k][2], a2);                                       \
            mac[k][3] = fminf(mac[k][3], a3);                                       \
        }

    // Software-pipelined mainloop: loads for g+1 issue before compute of g.
    #pragma unroll 1
    for (int g = 0; g < NGROUPS; g += 2) {
        load_grp(B, sa + 64);              // prefetch g+1
        COMPUTE(A);                        // compute g
        load_grp(A, sa + 128);             // prefetch g+2 (pad group on last iter)
        COMPUTE(B);                        // compute g+1
        sa += 128;
    }
    #undef COMPUTE

    // Write per-query partial (qsq + min over this ref slice).
    const size_t obase = (size_t)(dir * BS + b) * NPTS;
    #pragma unroll
    for (int k = 0; k < Q; ++k) {
        float m = fminf(fminf(mac[k][0], mac[k][1]), fminf(mac[k][2], mac[k][3]));
        g_pmin[(obase + (qbase + k * TPB)) * RS + rs] = qsq[k] + m;
    }

    // ---- Distributed epilogue: last RS-block of each group combines. ----
    const int gidx = (dir * BS + b) * NQT + qt;
    __threadfence();
    if (tid == 0)
        s_last = (atomicAdd(&g_gc[gidx], 1u) == RS - 1) ? 1 : 0;
    __syncthreads();

    if (s_last) {
        if (tid == 0) g_gc[gidx] = 0;     // self-reset for graph replay
        const float4* pm = (const float4*)g_pmin;   // RS=4 partials per query
        float v = 0.0f;
        #pragma unroll
        for (int k = 0; k < Q; ++k) {
            float4 p = __ldcg(pm + (obase + (qbase + k * TPB)));
            float m = fminf(fminf(p.x, p.y), fminf(p.z, p.w));
            v += sqrtf(1e-6f + m);
        }
        #pragma unroll
        for (int off = 16; off; off >>= 1)
            v += __shfl_down_sync(0xFFFFFFFFu, v, off);
        if ((tid & 31) == 0) red[tid >> 5] = v;
        __syncthreads();
        if (tid == 0) {
            float t = 0.0f;
            #pragma unroll
            for (int i = 0; i < 8; ++i) t += red[i];
            g_gsum[gidx] = t;
            __threadfence();
            if (atomicAdd(&g_fc, 1u) == NGRP - 1) {
                float tot = 0.0f;
                volatile float* gs = g_gsum;
                #pragma unroll
                for (int i = 0; i < NGRP; ++i) tot += gs[i];
                out[0] = tot * (1.0f / 16384.0f);   // (S1 + S2) / (BS * NPTS)
                g_fc = 0;                            // self-reset for graph replay
            }
        }
    }
}

extern "C" void kernel_launch(void* const* d_in, const int* in_sizes, int n_in,
                              void* d_out, int out_size)
{
    const float* x = (const float*)d_in[0];
    const float* y = (const float*)d_in[1];
    float* out = (float*)d_out;

    chamfer_main<<<dim3(NQT, BS, 2 * RS), TPB>>>(x, y, out);
}